// round 11
// baseline (speedup 1.0000x reference)
#include <cuda_runtime.h>
#include <cuda_fp16.h>
#include <cstdint>

#define BB 16
#define TT 250
#define EE 512
#define HH 1024
#define VV 32000
#define MM 4000          // B*T
#define H3 3072          // 3*H

// ---------------- device scratch ----------------
__device__ __half g_Wt[(size_t)H3 * EE];        // W^T  [3072][512]
__device__ __half g_Ut[(size_t)H3 * HH];        // U^T  [3072][1024]
__device__ __half g_Wot[(size_t)VV * HH];       // Wo^T [32000][1024]
__device__ __half g_x[(size_t)MM * EE];         // gathered embeddings fp16
__device__ float  g_xproj[(size_t)MM * H3];     // x@W + b_in (fp32)
__device__ __half g_hs[(size_t)MM * HH];        // all hidden states (fp16)
__device__ __half g_h[2][BB * HH];              // double-buffered h broadcast
__device__ unsigned g_bars[8 * 128];            // striped barrier counters (512B apart)

// ---------------- PTX helpers ----------------
__device__ __forceinline__ void ldsm4(unsigned &r0, unsigned &r1, unsigned &r2, unsigned &r3,
                                      const __half* p){
    unsigned a = (unsigned)__cvta_generic_to_shared((void*)p);
    asm volatile("ldmatrix.sync.aligned.m8n8.x4.shared.b16 {%0,%1,%2,%3},[%4];"
        : "=r"(r0), "=r"(r1), "=r"(r2), "=r"(r3) : "r"(a));
}
__device__ __forceinline__ void ldsm2(unsigned &r0, unsigned &r1, const __half* p){
    unsigned a = (unsigned)__cvta_generic_to_shared((void*)p);
    asm volatile("ldmatrix.sync.aligned.m8n8.x2.shared.b16 {%0,%1},[%2];"
        : "=r"(r0), "=r"(r1) : "r"(a));
}
__device__ __forceinline__ void mma16816(float* c, unsigned a0, unsigned a1, unsigned a2, unsigned a3,
                                         unsigned b0, unsigned b1){
    asm volatile("mma.sync.aligned.m16n8k16.row.col.f32.f16.f16.f32 "
        "{%0,%1,%2,%3},{%4,%5,%6,%7},{%8,%9},{%0,%1,%2,%3};"
        : "+f"(c[0]), "+f"(c[1]), "+f"(c[2]), "+f"(c[3])
        : "r"(a0), "r"(a1), "r"(a2), "r"(a3), "r"(b0), "r"(b1));
}
__device__ __forceinline__ void cp_async16(void* dst, const void* src){
    unsigned d = (unsigned)__cvta_generic_to_shared(dst);
    asm volatile("cp.async.cg.shared.global [%0],[%1],16;" :: "r"(d), "l"(src));
}

// ---------------- prep kernels ----------------
__global__ void transpose_all(const float* __restrict__ W, const float* __restrict__ U,
                              const float* __restrict__ Wo){
    const float* in; __half* out; int K, N;
    if (blockIdx.z == 0){ in = W;  out = g_Wt;  K = EE; N = H3; }
    else if (blockIdx.z == 1){ in = U;  out = g_Ut;  K = HH; N = H3; }
    else               { in = Wo; out = g_Wot; K = HH; N = VV; }
    int n0 = blockIdx.x * 32, k0 = blockIdx.y * 32;
    if (n0 >= N || k0 >= K) return;
    __shared__ float tile[32][33];
    int tx = threadIdx.x, ty = threadIdx.y;
    #pragma unroll
    for (int i = 0; i < 32; i += 8)
        tile[ty + i][tx] = in[(size_t)(k0 + ty + i) * N + n0 + tx];
    __syncthreads();
    #pragma unroll
    for (int i = 0; i < 32; i += 8)
        out[(size_t)(n0 + ty + i) * K + k0 + tx] = __float2half(tile[tx][ty + i]);
}

__global__ void gather_init(const int* __restrict__ tok, const float* __restrict__ emb,
                            const float* __restrict__ h0){
    int m = blockIdx.x, tix = threadIdx.x;
    if (m == 0){                                   // zero striped barrier counters
        #pragma unroll
        for (int i = 0; i < 8; i++)
            if (tix < 128) g_bars[i * 128 + tix] = 0u;   // full clear (only [i*128] used)
    }
    int gi = m * 128 + tix;
    if (gi < BB * HH) g_h[0][gi] = __float2half(h0[gi]);
    int e = tix * 4;
    int t = tok[m];
    float4 v = *(const float4*)(emb + (size_t)t * EE + e);
    *(__half2*)(g_x + (size_t)m * EE + e)     = __floats2half2_rn(v.x, v.y);
    *(__half2*)(g_x + (size_t)m * EE + e + 2) = __floats2half2_rn(v.z, v.w);
}

// ---------------- fp16 mma GEMM (R6 shape: 128x128, occ 2, 3-stage) ----------------
#define GBM 128
#define GBN 128
#define GBK 32
#define AROW 40
#define ASTG (GBM * AROW)
#define NSTG 3
#define GSMEM (NSTG * ASTG * 2 * 2)   // 61440 B

__global__ __launch_bounds__(256, 2)
void gemm_f16(const __half* __restrict__ A, const __half* __restrict__ Bm,
              const float* __restrict__ bias, float* __restrict__ C,
              int M, int N, int K)
{
    extern __shared__ __half gsm[];
    __half* As = gsm;
    __half* Bs = gsm + NSTG * ASTG;
    const int tid = threadIdx.x;
    const int m0 = blockIdx.y * GBM, n0 = blockIdx.x * GBN;
    const int warp = tid >> 5, lane = tid & 31;
    const int wm = warp >> 2, wn = warp & 3;

    float acc[4][4][4] = {};
    const int KT = K / GBK;

    auto stage_ld = [&](int st, int kt){
        const int k0 = kt * GBK;
        #pragma unroll
        for (int i = 0; i < 2; i++){
            int c = tid + i * 256;
            int row = c >> 2, sg = c & 3;
            int ar = m0 + row; if (ar >= M) ar = M - 1;
            cp_async16(&As[st * ASTG + row * AROW + sg * 8], A  + (size_t)ar * K         + k0 + sg * 8);
            cp_async16(&Bs[st * ASTG + row * AROW + sg * 8], Bm + (size_t)(n0 + row) * K + k0 + sg * 8);
        }
    };

    stage_ld(0, 0);
    asm volatile("cp.async.commit_group;");
    if (KT > 1){ stage_ld(1, 1); asm volatile("cp.async.commit_group;"); }

    for (int kt = 0; kt < KT; ++kt){
        const int st = kt % NSTG;
        if (kt < KT - 1) asm volatile("cp.async.wait_group 1;");
        else             asm volatile("cp.async.wait_group 0;");
        __syncthreads();
        if (kt + 2 < KT){
            stage_ld((kt + 2) % NSTG, kt + 2);
            asm volatile("cp.async.commit_group;");
        }
        #pragma unroll
        for (int kk = 0; kk < 2; kk++){
            unsigned a[4][4];
            #pragma unroll
            for (int mi = 0; mi < 4; mi++){
                const __half* p = &As[st * ASTG + (wm * 64 + mi * 16 + (lane & 15)) * AROW
                                      + kk * 16 + (lane >> 4) * 8];
                ldsm4(a[mi][0], a[mi][1], a[mi][2], a[mi][3], p);
            }
            unsigned bfr[2][4];
            #pragma unroll
            for (int nj = 0; nj < 2; nj++){
                const __half* p = &Bs[st * ASTG + (wn * 32 + nj * 16 + (lane & 15)) * AROW
                                      + kk * 16 + (lane >> 4) * 8];
                ldsm4(bfr[nj][0], bfr[nj][1], bfr[nj][2], bfr[nj][3], p);
            }
            #pragma unroll
            for (int mi = 0; mi < 4; mi++)
                #pragma unroll
                for (int ni = 0; ni < 4; ni++){
                    unsigned b0 = bfr[ni >> 1][(ni & 1)];
                    unsigned b1 = bfr[ni >> 1][(ni & 1) + 2];
                    mma16816(acc[mi][ni], a[mi][0], a[mi][1], a[mi][2], a[mi][3], b0, b1);
                }
        }
    }

    const int mrow0 = m0 + wm * 64;
    #pragma unroll
    for (int mi = 0; mi < 4; mi++)
        #pragma unroll
        for (int ni = 0; ni < 4; ni++){
            int r0 = mrow0 + mi * 16 + (lane >> 2);
            int cc = n0 + wn * 32 + ni * 8 + (lane & 3) * 2;
            float b0f = bias[cc], b1f = bias[cc + 1];
            if (r0 < M){
                float2 v = {acc[mi][ni][0] + b0f, acc[mi][ni][1] + b1f};
                *(float2*)&C[(size_t)r0 * N + cc] = v;
            }
            int r1 = r0 + 8;
            if (r1 < M){
                float2 v = {acc[mi][ni][2] + b0f, acc[mi][ni][3] + b1f};
                *(float2*)&C[(size_t)r1 * N + cc] = v;
            }
        }
}

// ---------------- persistent GRU scan: 128 CTAs x 384 threads ----------------
// CTA owns 8 hidden units; 12 warps: nt = wid>>2 (0..2, 8-col n-tile),
// kq = wid&3 (256-wide k quarter) -> 16-deep mma chain per warp.
// Barrier: 8 striped L2 counters (512B apart), arrival red.release, poll sums.
#define SC_CTAS 128
#define SC_THREADS 384
#define HSTR 1032

__global__ __launch_bounds__(SC_THREADS, 1)
void gru_scan(const float* __restrict__ brec, const float* __restrict__ h0)
{
    extern __shared__ __half sdyn[];
    __half* hU = sdyn;                          // 24 * HSTR halves
    __half* hA = hU + 24 * HSTR;                // 16 * HSTR halves
    float*  rec = (float*)(hA + 16 * HSTR);     // [4][16][24]

    const int tid = threadIdx.x;
    const int cta = blockIdx.x;
    const int wid = tid >> 5, lane = tid & 31;
    const int nt = wid >> 2;    // 0..2
    const int kq = wid & 3;     // k quarter
    float* recw = rec + kq * (16 * 24);

    for (int c = tid; c < 24 * 128; c += SC_THREADS){
        int j = c >> 7, seg = (c & 127) * 8;
        int gate = j >> 3, u = j & 7;
        *(int4*)&hU[j * HSTR + seg] =
            *(const int4*)&g_Ut[(size_t)(gate * HH + cta * 8 + u) * HH + seg];
    }

    float h_state = 0.f, bz = 0.f, br_ = 0.f, bh = 0.f;
    float xzc = 0.f, xrc = 0.f, xhc = 0.f;
    int b = 0, u = 0, iglob = 0;
    if (tid < 128){
        b = tid >> 3; u = tid & 7; iglob = cta * 8 + u;
        h_state = h0[b * HH + iglob];
        bz  = brec[iglob];
        br_ = brec[HH + iglob];
        bh  = brec[2 * HH + iglob];
        const size_t xrow = (size_t)(b * TT + 0) * H3;
        xzc = __ldcg(&g_xproj[xrow + iglob]);
        xrc = __ldcg(&g_xproj[xrow + HH + iglob]);
        xhc = __ldcg(&g_xproj[xrow + 2 * HH + iglob]);
    }
    __syncthreads();

    const __half* pa_base = hA + (lane & 15) * HSTR + (lane >> 4) * 8;
    const __half* pb_base = hU + (nt * 8 + (lane & 7)) * HSTR + ((lane >> 3) & 1) * 8;
    unsigned* my_ctr = &g_bars[(cta & 7) * 128];

    for (int t = 0; t < TT; ++t){
        const int cur = t & 1, nxt = cur ^ 1;

        // stage h[16][1024] fp16 into smem (bypass non-coherent L1)
        for (int c = tid; c < 16 * 128; c += SC_THREADS){
            int row = c >> 7, seg = (c & 127) * 8;
            int4 v = __ldcv((const int4*)&g_h[cur][row * HH + seg]);
            *(int4*)&hA[row * HSTR + seg] = v;
        }
        __syncthreads();

        // rec[kq] = h[16, kquarter] @ Ustrip[nt rows, kquarter]^T  (16-deep chain)
        float a4[4][4] = {};
        #pragma unroll
        for (int ks = 0; ks < 16; ++ks){
            int gk = kq * 16 + ks;
            unsigned A0, A1, A2, A3, B0, B1;
            ldsm4(A0, A1, A2, A3, pa_base + gk * 16);
            ldsm2(B0, B1, pb_base + gk * 16);
            mma16816(a4[ks & 3], A0, A1, A2, A3, B0, B1);
        }
        #pragma unroll
        for (int i = 0; i < 4; i++) a4[0][i] += a4[1][i] + a4[2][i] + a4[3][i];

        {
            int r = lane >> 2, c = nt * 8 + (lane & 3) * 2;
            recw[r * 24 + c]           = a4[0][0];
            recw[r * 24 + c + 1]       = a4[0][1];
            recw[(r + 8) * 24 + c]     = a4[0][2];
            recw[(r + 8) * 24 + c + 1] = a4[0][3];
        }
        __syncthreads();

        if (tid < 128){
            float rz = bz, rr = br_, rh = bh;
            #pragma unroll
            for (int q = 0; q < 4; q++){
                const float* rq = rec + q * (16 * 24) + b * 24;
                rz += rq[u];
                rr += rq[8 + u];
                rh += rq[16 + u];
            }
            float z  = 1.f / (1.f + __expf(-(xzc + rz)));
            float r_ = 1.f / (1.f + __expf(-(xrc + rr)));
            float hh = tanhf(xhc + r_ * rh);
            h_state = z * h_state + (1.f - z) * hh;
            __half hv = __float2half(h_state);
            g_h[nxt][b * HH + iglob] = hv;
            g_hs[(size_t)(b * TT + t) * HH + iglob] = hv;
            if (t + 1 < TT){     // prefetch next step's x-projection before the barrier
                const size_t xrow = (size_t)(b * TT + t + 1) * H3;
                xzc = __ldcg(&g_xproj[xrow + iglob]);
                xrc = __ldcg(&g_xproj[xrow + HH + iglob]);
                xhc = __ldcg(&g_xproj[xrow + 2 * HH + iglob]);
            }
        }
        if (t < TT - 1){
            __syncthreads();      // order all CTA stores before the release-add
            if (tid == 0){
                asm volatile("red.release.gpu.global.add.u32 [%0], 1;"
                    :: "l"(my_ctr) : "memory");
                const unsigned tgt = (unsigned)(SC_CTAS * (t + 1));
                unsigned s;
                do {
                    unsigned v0, v1, v2, v3, v4, v5, v6, v7;
                    asm volatile("ld.acquire.gpu.global.u32 %0, [%1];" : "=r"(v0) : "l"(&g_bars[0*128]));
                    asm volatile("ld.acquire.gpu.global.u32 %0, [%1];" : "=r"(v1) : "l"(&g_bars[1*128]));
                    asm volatile("ld.acquire.gpu.global.u32 %0, [%1];" : "=r"(v2) : "l"(&g_bars[2*128]));
                    asm volatile("ld.acquire.gpu.global.u32 %0, [%1];" : "=r"(v3) : "l"(&g_bars[3*128]));
                    asm volatile("ld.acquire.gpu.global.u32 %0, [%1];" : "=r"(v4) : "l"(&g_bars[4*128]));
                    asm volatile("ld.acquire.gpu.global.u32 %0, [%1];" : "=r"(v5) : "l"(&g_bars[5*128]));
                    asm volatile("ld.acquire.gpu.global.u32 %0, [%1];" : "=r"(v6) : "l"(&g_bars[6*128]));
                    asm volatile("ld.acquire.gpu.global.u32 %0, [%1];" : "=r"(v7) : "l"(&g_bars[7*128]));
                    s = v0 + v1 + v2 + v3 + v4 + v5 + v6 + v7;
                } while (s < tgt);
            }
            __syncthreads();
        }
    }
}

// ---------------- launch ----------------
extern "C" void kernel_launch(void* const* d_in, const int* in_sizes, int n_in,
                              void* d_out, int out_size)
{
    const int*   tok = (const int*)  d_in[0];
    const float* h0  = (const float*)d_in[1];
    const float* emb = (const float*)d_in[2];
    const float* W   = (const float*)d_in[3];
    const float* U   = (const float*)d_in[4];
    const float* bb  = (const float*)d_in[5];
    const float* Wo  = (const float*)d_in[6];
    const float* bo  = (const float*)d_in[7];
    float* out = (float*)d_out;

    void *pWt, *pUt, *pWot, *px, *pxp, *phs;
    cudaGetSymbolAddress(&pWt,  g_Wt);
    cudaGetSymbolAddress(&pUt,  g_Ut);
    cudaGetSymbolAddress(&pWot, g_Wot);
    cudaGetSymbolAddress(&px,   g_x);
    cudaGetSymbolAddress(&pxp,  g_xproj);
    cudaGetSymbolAddress(&phs,  g_hs);

    cudaFuncSetAttribute(gemm_f16, cudaFuncAttributeMaxDynamicSharedMemorySize, GSMEM);
    const int scan_smem = (24 + 16) * HSTR * (int)sizeof(__half)
                        + 4 * 16 * 24 * (int)sizeof(float);   // 88704 B
    cudaFuncSetAttribute(gru_scan, cudaFuncAttributeMaxDynamicSharedMemorySize, scan_smem);

    transpose_all<<<dim3(VV / 32, 32, 3), dim3(32, 8)>>>(W, U, Wo);
    gather_init<<<MM, 128>>>(tok, emb, h0);
    // x_proj = x @ W + b[0]   (M=4000, N=3072, K=512)
    gemm_f16<<<dim3(H3 / GBN, (MM + GBM - 1) / GBM), 256, GSMEM>>>(
        (const __half*)px, (const __half*)pWt, bb, (float*)pxp, MM, H3, EE);
    // GRU scan (persistent, grid-barriered)
    gru_scan<<<SC_CTAS, SC_THREADS, scan_smem>>>(bb + H3, h0);
    // logits = hs @ Wo + bo   (M=4000, N=32000, K=1024)
    gemm_f16<<<dim3(VV / GBN, (MM + GBM - 1) / GBM), 256, GSMEM>>>(
        (const __half*)phs, (const __half*)pWot, bo, out, MM, VV, HH);
}

// round 12
// speedup vs baseline: 1.0357x; 1.0357x over previous
#include <cuda_runtime.h>
#include <cuda_fp16.h>
#include <cstdint>

#define BB 16
#define TT 250
#define EE 512
#define HH 1024
#define VV 32000
#define MM 4000          // B*T
#define H3 3072          // 3*H

// ---------------- device scratch ----------------
__device__ __half g_Wt[(size_t)H3 * EE];        // W^T  [3072][512]
__device__ __half g_Ut[(size_t)H3 * HH];        // U^T  [3072][1024]
__device__ __half g_Wot[(size_t)VV * HH];       // Wo^T [32000][1024]
__device__ __half g_x[(size_t)MM * EE];         // gathered embeddings fp16
__device__ float  g_xproj[(size_t)MM * H3];     // x@W + b_in (fp32)
__device__ __half g_hs[(size_t)MM * HH];        // all hidden states (fp16)
__device__ __half g_h[2][BB * HH];              // double-buffered h broadcast
__device__ unsigned g_bars[8 * 128];            // striped barrier counters (512B apart)

// ---------------- PTX helpers ----------------
__device__ __forceinline__ void ldsm4(unsigned &r0, unsigned &r1, unsigned &r2, unsigned &r3,
                                      const __half* p){
    unsigned a = (unsigned)__cvta_generic_to_shared((void*)p);
    asm volatile("ldmatrix.sync.aligned.m8n8.x4.shared.b16 {%0,%1,%2,%3},[%4];"
        : "=r"(r0), "=r"(r1), "=r"(r2), "=r"(r3) : "r"(a));
}
__device__ __forceinline__ void ldsm2(unsigned &r0, unsigned &r1, const __half* p){
    unsigned a = (unsigned)__cvta_generic_to_shared((void*)p);
    asm volatile("ldmatrix.sync.aligned.m8n8.x2.shared.b16 {%0,%1},[%2];"
        : "=r"(r0), "=r"(r1) : "r"(a));
}
__device__ __forceinline__ void mma16816(float* c, unsigned a0, unsigned a1, unsigned a2, unsigned a3,
                                         unsigned b0, unsigned b1){
    asm volatile("mma.sync.aligned.m16n8k16.row.col.f32.f16.f16.f32 "
        "{%0,%1,%2,%3},{%4,%5,%6,%7},{%8,%9},{%0,%1,%2,%3};"
        : "+f"(c[0]), "+f"(c[1]), "+f"(c[2]), "+f"(c[3])
        : "r"(a0), "r"(a1), "r"(a2), "r"(a3), "r"(b0), "r"(b1));
}
__device__ __forceinline__ void cp_async16(void* dst, const void* src){
    unsigned d = (unsigned)__cvta_generic_to_shared(dst);
    asm volatile("cp.async.cg.shared.global [%0],[%1],16;" :: "r"(d), "l"(src));
}

// ---------------- prep kernels ----------------
__global__ void transpose_all(const float* __restrict__ W, const float* __restrict__ U,
                              const float* __restrict__ Wo){
    const float* in; __half* out; int K, N;
    if (blockIdx.z == 0){ in = W;  out = g_Wt;  K = EE; N = H3; }
    else if (blockIdx.z == 1){ in = U;  out = g_Ut;  K = HH; N = H3; }
    else               { in = Wo; out = g_Wot; K = HH; N = VV; }
    int n0 = blockIdx.x * 32, k0 = blockIdx.y * 32;
    if (n0 >= N || k0 >= K) return;
    __shared__ float tile[32][33];
    int tx = threadIdx.x, ty = threadIdx.y;
    #pragma unroll
    for (int i = 0; i < 32; i += 8)
        tile[ty + i][tx] = in[(size_t)(k0 + ty + i) * N + n0 + tx];
    __syncthreads();
    #pragma unroll
    for (int i = 0; i < 32; i += 8)
        out[(size_t)(n0 + ty + i) * K + k0 + tx] = __float2half(tile[tx][ty + i]);
}

__global__ void gather_init(const int* __restrict__ tok, const float* __restrict__ emb,
                            const float* __restrict__ h0){
    int m = blockIdx.x, tix = threadIdx.x;
    if (m == 0 && tix < 128){                      // zero striped barrier counters
        #pragma unroll
        for (int i = 0; i < 8; i++) g_bars[i * 128 + tix] = 0u;
    }
    int gi = m * 128 + tix;
    if (gi < BB * HH) g_h[0][gi] = __float2half(h0[gi]);
    int e = tix * 4;
    int t = tok[m];
    float4 v = *(const float4*)(emb + (size_t)t * EE + e);
    *(__half2*)(g_x + (size_t)m * EE + e)     = __floats2half2_rn(v.x, v.y);
    *(__half2*)(g_x + (size_t)m * EE + e + 2) = __floats2half2_rn(v.z, v.w);
}

// ---------------- fp16 mma GEMM (R6 shape: 128x128, occ 2, 3-stage) ----------------
#define GBM 128
#define GBN 128
#define GBK 32
#define AROW 40
#define ASTG (GBM * AROW)
#define NSTG 3
#define GSMEM (NSTG * ASTG * 2 * 2)   // 61440 B

__global__ __launch_bounds__(256, 2)
void gemm_f16(const __half* __restrict__ A, const __half* __restrict__ Bm,
              const float* __restrict__ bias, float* __restrict__ C,
              int M, int N, int K)
{
    extern __shared__ __half gsm[];
    __half* As = gsm;
    __half* Bs = gsm + NSTG * ASTG;
    const int tid = threadIdx.x;
    const int m0 = blockIdx.y * GBM, n0 = blockIdx.x * GBN;
    const int warp = tid >> 5, lane = tid & 31;
    const int wm = warp >> 2, wn = warp & 3;

    float acc[4][4][4] = {};
    const int KT = K / GBK;

    auto stage_ld = [&](int st, int kt){
        const int k0 = kt * GBK;
        #pragma unroll
        for (int i = 0; i < 2; i++){
            int c = tid + i * 256;
            int row = c >> 2, sg = c & 3;
            int ar = m0 + row; if (ar >= M) ar = M - 1;
            cp_async16(&As[st * ASTG + row * AROW + sg * 8], A  + (size_t)ar * K         + k0 + sg * 8);
            cp_async16(&Bs[st * ASTG + row * AROW + sg * 8], Bm + (size_t)(n0 + row) * K + k0 + sg * 8);
        }
    };

    stage_ld(0, 0);
    asm volatile("cp.async.commit_group;");
    if (KT > 1){ stage_ld(1, 1); asm volatile("cp.async.commit_group;"); }

    for (int kt = 0; kt < KT; ++kt){
        const int st = kt % NSTG;
        if (kt < KT - 1) asm volatile("cp.async.wait_group 1;");
        else             asm volatile("cp.async.wait_group 0;");
        __syncthreads();
        if (kt + 2 < KT){
            stage_ld((kt + 2) % NSTG, kt + 2);
            asm volatile("cp.async.commit_group;");
        }
        #pragma unroll
        for (int kk = 0; kk < 2; kk++){
            unsigned a[4][4];
            #pragma unroll
            for (int mi = 0; mi < 4; mi++){
                const __half* p = &As[st * ASTG + (wm * 64 + mi * 16 + (lane & 15)) * AROW
                                      + kk * 16 + (lane >> 4) * 8];
                ldsm4(a[mi][0], a[mi][1], a[mi][2], a[mi][3], p);
            }
            unsigned bfr[2][4];
            #pragma unroll
            for (int nj = 0; nj < 2; nj++){
                const __half* p = &Bs[st * ASTG + (wn * 32 + nj * 16 + (lane & 15)) * AROW
                                      + kk * 16 + (lane >> 4) * 8];
                ldsm4(bfr[nj][0], bfr[nj][1], bfr[nj][2], bfr[nj][3], p);
            }
            #pragma unroll
            for (int mi = 0; mi < 4; mi++)
                #pragma unroll
                for (int ni = 0; ni < 4; ni++){
                    unsigned b0 = bfr[ni >> 1][(ni & 1)];
                    unsigned b1 = bfr[ni >> 1][(ni & 1) + 2];
                    mma16816(acc[mi][ni], a[mi][0], a[mi][1], a[mi][2], a[mi][3], b0, b1);
                }
        }
    }

    const int mrow0 = m0 + wm * 64;
    #pragma unroll
    for (int mi = 0; mi < 4; mi++)
        #pragma unroll
        for (int ni = 0; ni < 4; ni++){
            int r0 = mrow0 + mi * 16 + (lane >> 2);
            int cc = n0 + wn * 32 + ni * 8 + (lane & 3) * 2;
            float b0f = bias[cc], b1f = bias[cc + 1];
            if (r0 < M){
                float2 v = {acc[mi][ni][0] + b0f, acc[mi][ni][1] + b1f};
                *(float2*)&C[(size_t)r0 * N + cc] = v;
            }
            int r1 = r0 + 8;
            if (r1 < M){
                float2 v = {acc[mi][ni][2] + b0f, acc[mi][ni][3] + b1f};
                *(float2*)&C[(size_t)r1 * N + cc] = v;
            }
        }
}

// ---------------- persistent GRU scan: 128 CTAs x 192 threads (R6 structure) -------
// CTA owns 8 hidden units; 6 warps: nt = warp>>1 (0..2), kh = warp&1 (512-wide half).
// Dual rec buffers (single sync); striped-counter release barrier; xproj prefetch.
#define SC_CTAS 128
#define SC_THREADS 192
#define HSTR 1032

__global__ __launch_bounds__(SC_THREADS, 1)
void gru_scan(const float* __restrict__ brec, const float* __restrict__ h0)
{
    extern __shared__ __half sdyn[];
    __half* hU = sdyn;                          // 24 * HSTR halves
    __half* hA = hU + 24 * HSTR;                // 16 * HSTR halves
    float*  rec0 = (float*)(hA + 16 * HSTR);    // [16][24] (kh=0)
    float*  rec1 = rec0 + 16 * 24;              // [16][24] (kh=1)

    const int tid = threadIdx.x;
    const int cta = blockIdx.x;
    const int warp = tid >> 5, lane = tid & 31;
    const int nt = warp >> 1;
    const int kh = warp & 1;
    float* recw = kh ? rec1 : rec0;

    for (int c = tid; c < 24 * 128; c += SC_THREADS){
        int j = c >> 7, seg = (c & 127) * 8;
        int gate = j >> 3, u = j & 7;
        *(int4*)&hU[j * HSTR + seg] =
            *(const int4*)&g_Ut[(size_t)(gate * HH + cta * 8 + u) * HH + seg];
    }

    float h_state = 0.f, bz = 0.f, br_ = 0.f, bh = 0.f;
    float xzc = 0.f, xrc = 0.f, xhc = 0.f;
    int b = 0, u = 0, iglob = 0;
    if (tid < 128){
        b = tid >> 3; u = tid & 7; iglob = cta * 8 + u;
        h_state = h0[b * HH + iglob];
        bz  = brec[iglob];
        br_ = brec[HH + iglob];
        bh  = brec[2 * HH + iglob];
        const size_t xrow = (size_t)(b * TT + 0) * H3;
        xzc = __ldcg(&g_xproj[xrow + iglob]);
        xrc = __ldcg(&g_xproj[xrow + HH + iglob]);
        xhc = __ldcg(&g_xproj[xrow + 2 * HH + iglob]);
    }
    __syncthreads();

    const __half* pa_base = hA + (lane & 15) * HSTR + (lane >> 4) * 8;
    const __half* pb_base = hU + (nt * 8 + (lane & 7)) * HSTR + ((lane >> 3) & 1) * 8;
    unsigned* my_ctr = &g_bars[(cta & 7) * 128];

    for (int t = 0; t < TT; ++t){
        const int cur = t & 1, nxt = cur ^ 1;

        // stage h[16][1024] fp16 into smem (bypass non-coherent L1)
        for (int c = tid; c < 16 * 128; c += SC_THREADS){
            int row = c >> 7, seg = (c & 127) * 8;
            int4 v = __ldcv((const int4*)&g_h[cur][row * HH + seg]);
            *(int4*)&hA[row * HSTR + seg] = v;
        }
        __syncthreads();

        // rec(kh) = h[16, khalf] @ Ustrip[24, khalf]^T  (4 rotating accums)
        float a4[4][4] = {};
        #pragma unroll
        for (int ks = 0; ks < 32; ++ks){
            int gk = kh * 32 + ks;
            unsigned A0, A1, A2, A3, B0, B1;
            ldsm4(A0, A1, A2, A3, pa_base + gk * 16);
            ldsm2(B0, B1, pb_base + gk * 16);
            mma16816(a4[ks & 3], A0, A1, A2, A3, B0, B1);
        }
        #pragma unroll
        for (int i = 0; i < 4; i++) a4[0][i] += a4[1][i] + a4[2][i] + a4[3][i];

        {
            int r = lane >> 2, c = nt * 8 + (lane & 3) * 2;
            recw[r * 24 + c]           = a4[0][0];
            recw[r * 24 + c + 1]       = a4[0][1];
            recw[(r + 8) * 24 + c]     = a4[0][2];
            recw[(r + 8) * 24 + c + 1] = a4[0][3];
        }
        __syncthreads();

        if (tid < 128){
            float rz = rec0[b * 24 + u]      + rec1[b * 24 + u]      + bz;
            float rr = rec0[b * 24 + 8 + u]  + rec1[b * 24 + 8 + u]  + br_;
            float rh = rec0[b * 24 + 16 + u] + rec1[b * 24 + 16 + u] + bh;
            float z  = 1.f / (1.f + __expf(-(xzc + rz)));
            float r_ = 1.f / (1.f + __expf(-(xrc + rr)));
            float hh = tanhf(xhc + r_ * rh);
            h_state = z * h_state + (1.f - z) * hh;
            __half hv = __float2half(h_state);
            g_h[nxt][b * HH + iglob] = hv;
            g_hs[(size_t)(b * TT + t) * HH + iglob] = hv;
            if (t + 1 < TT){     // prefetch next step's x-projection before the barrier
                const size_t xrow = (size_t)(b * TT + t + 1) * H3;
                xzc = __ldcg(&g_xproj[xrow + iglob]);
                xrc = __ldcg(&g_xproj[xrow + HH + iglob]);
                xhc = __ldcg(&g_xproj[xrow + 2 * HH + iglob]);
            }
        }
        if (t < TT - 1){
            __syncthreads();      // order all CTA stores before the release-add
            if (tid == 0){
                asm volatile("red.release.gpu.global.add.u32 [%0], 1;"
                    :: "l"(my_ctr) : "memory");
                const unsigned tgt = (unsigned)(SC_CTAS * (t + 1));
                unsigned s;
                do {
                    unsigned v0, v1, v2, v3, v4, v5, v6, v7;
                    asm volatile("ld.acquire.gpu.global.u32 %0, [%1];" : "=r"(v0) : "l"(&g_bars[0*128]));
                    asm volatile("ld.acquire.gpu.global.u32 %0, [%1];" : "=r"(v1) : "l"(&g_bars[1*128]));
                    asm volatile("ld.acquire.gpu.global.u32 %0, [%1];" : "=r"(v2) : "l"(&g_bars[2*128]));
                    asm volatile("ld.acquire.gpu.global.u32 %0, [%1];" : "=r"(v3) : "l"(&g_bars[3*128]));
                    asm volatile("ld.acquire.gpu.global.u32 %0, [%1];" : "=r"(v4) : "l"(&g_bars[4*128]));
                    asm volatile("ld.acquire.gpu.global.u32 %0, [%1];" : "=r"(v5) : "l"(&g_bars[5*128]));
                    asm volatile("ld.acquire.gpu.global.u32 %0, [%1];" : "=r"(v6) : "l"(&g_bars[6*128]));
                    asm volatile("ld.acquire.gpu.global.u32 %0, [%1];" : "=r"(v7) : "l"(&g_bars[7*128]));
                    s = v0 + v1 + v2 + v3 + v4 + v5 + v6 + v7;
                } while (s < tgt);
            }
            __syncthreads();
        }
    }
}

// ---------------- launch ----------------
extern "C" void kernel_launch(void* const* d_in, const int* in_sizes, int n_in,
                              void* d_out, int out_size)
{
    const int*   tok = (const int*)  d_in[0];
    const float* h0  = (const float*)d_in[1];
    const float* emb = (const float*)d_in[2];
    const float* W   = (const float*)d_in[3];
    const float* U   = (const float*)d_in[4];
    const float* bb  = (const float*)d_in[5];
    const float* Wo  = (const float*)d_in[6];
    const float* bo  = (const float*)d_in[7];
    float* out = (float*)d_out;

    void *pWt, *pUt, *pWot, *px, *pxp, *phs;
    cudaGetSymbolAddress(&pWt,  g_Wt);
    cudaGetSymbolAddress(&pUt,  g_Ut);
    cudaGetSymbolAddress(&pWot, g_Wot);
    cudaGetSymbolAddress(&px,   g_x);
    cudaGetSymbolAddress(&pxp,  g_xproj);
    cudaGetSymbolAddress(&phs,  g_hs);

    cudaFuncSetAttribute(gemm_f16, cudaFuncAttributeMaxDynamicSharedMemorySize, GSMEM);
    const int scan_smem = (24 + 16) * HSTR * (int)sizeof(__half)
                        + 2 * 16 * 24 * (int)sizeof(float);   // 85632 B
    cudaFuncSetAttribute(gru_scan, cudaFuncAttributeMaxDynamicSharedMemorySize, scan_smem);

    transpose_all<<<dim3(VV / 32, 32, 3), dim3(32, 8)>>>(W, U, Wo);
    gather_init<<<MM, 128>>>(tok, emb, h0);
    // x_proj = x @ W + b[0]   (M=4000, N=3072, K=512)
    gemm_f16<<<dim3(H3 / GBN, (MM + GBM - 1) / GBM), 256, GSMEM>>>(
        (const __half*)px, (const __half*)pWt, bb, (float*)pxp, MM, H3, EE);
    // GRU scan (persistent, grid-barriered)
    gru_scan<<<SC_CTAS, SC_THREADS, scan_smem>>>(bb + H3, h0);
    // logits = hs @ Wo + bo   (M=4000, N=32000, K=1024)
    gemm_f16<<<dim3(VV / GBN, (MM + GBM - 1) / GBM), 256, GSMEM>>>(
        (const __half*)phs, (const __half*)pWot, bo, out, MM, VV, HH);
}

// round 13
// speedup vs baseline: 1.3907x; 1.3428x over previous
#include <cuda_runtime.h>
#include <cuda_fp16.h>
#include <cstdint>

#define BB 16
#define TT 250
#define EE 512
#define HH 1024
#define VV 32000
#define MM 4000          // B*T
#define H3 3072          // 3*H

// ---------------- device scratch ----------------
__device__ __half g_Wt[(size_t)H3 * EE];        // W^T  [3072][512]
__device__ __half g_Ut[(size_t)H3 * HH];        // U^T  [3072][1024]
__device__ __half g_Wot[(size_t)VV * HH];       // Wo^T [32000][1024]
__device__ __half g_x[(size_t)MM * EE];         // gathered embeddings fp16
__device__ float  g_xproj[(size_t)MM * H3];     // x@W + b_in (fp32)
__device__ __half g_hs[(size_t)MM * HH];        // all hidden states (fp16)
__device__ __half g_h[2][BB * HH];              // double-buffered h broadcast
__device__ unsigned g_bar;                      // grid barrier counter

// ---------------- PTX helpers ----------------
__device__ __forceinline__ void ldsm4(unsigned &r0, unsigned &r1, unsigned &r2, unsigned &r3,
                                      const __half* p){
    unsigned a = (unsigned)__cvta_generic_to_shared((void*)p);
    asm volatile("ldmatrix.sync.aligned.m8n8.x4.shared.b16 {%0,%1,%2,%3},[%4];"
        : "=r"(r0), "=r"(r1), "=r"(r2), "=r"(r3) : "r"(a));
}
__device__ __forceinline__ void ldsm2(unsigned &r0, unsigned &r1, const __half* p){
    unsigned a = (unsigned)__cvta_generic_to_shared((void*)p);
    asm volatile("ldmatrix.sync.aligned.m8n8.x2.shared.b16 {%0,%1},[%2];"
        : "=r"(r0), "=r"(r1) : "r"(a));
}
__device__ __forceinline__ void mma16816(float* c, unsigned a0, unsigned a1, unsigned a2, unsigned a3,
                                         unsigned b0, unsigned b1){
    asm volatile("mma.sync.aligned.m16n8k16.row.col.f32.f16.f16.f32 "
        "{%0,%1,%2,%3},{%4,%5,%6,%7},{%8,%9},{%0,%1,%2,%3};"
        : "+f"(c[0]), "+f"(c[1]), "+f"(c[2]), "+f"(c[3])
        : "r"(a0), "r"(a1), "r"(a2), "r"(a3), "r"(b0), "r"(b1));
}
__device__ __forceinline__ void cp_async16(void* dst, const void* src){
    unsigned d = (unsigned)__cvta_generic_to_shared(dst);
    asm volatile("cp.async.cg.shared.global [%0],[%1],16;" :: "r"(d), "l"(src));
}

// ---------------- prep kernels ----------------
__global__ void transpose_all(const float* __restrict__ W, const float* __restrict__ U,
                              const float* __restrict__ Wo){
    const float* in; __half* out; int K, N;
    if (blockIdx.z == 0){ in = W;  out = g_Wt;  K = EE; N = H3; }
    else if (blockIdx.z == 1){ in = U;  out = g_Ut;  K = HH; N = H3; }
    else               { in = Wo; out = g_Wot; K = HH; N = VV; }
    int n0 = blockIdx.x * 32, k0 = blockIdx.y * 32;
    if (n0 >= N || k0 >= K) return;
    __shared__ float tile[32][33];
    int tx = threadIdx.x, ty = threadIdx.y;
    #pragma unroll
    for (int i = 0; i < 32; i += 8)
        tile[ty + i][tx] = in[(size_t)(k0 + ty + i) * N + n0 + tx];
    __syncthreads();
    #pragma unroll
    for (int i = 0; i < 32; i += 8)
        out[(size_t)(n0 + ty + i) * K + k0 + tx] = __float2half(tile[tx][ty + i]);
}

__global__ void gather_init(const int* __restrict__ tok, const float* __restrict__ emb,
                            const float* __restrict__ h0){
    int m = blockIdx.x, tix = threadIdx.x;
    if (m == 0 && tix == 0) g_bar = 0u;
    int gi = m * 128 + tix;
    if (gi < BB * HH) g_h[0][gi] = __float2half(h0[gi]);
    int e = tix * 4;
    int t = tok[m];
    float4 v = *(const float4*)(emb + (size_t)t * EE + e);
    *(__half2*)(g_x + (size_t)m * EE + e)     = __floats2half2_rn(v.x, v.y);
    *(__half2*)(g_x + (size_t)m * EE + e + 2) = __floats2half2_rn(v.z, v.w);
}

// ---------------- fp16 mma GEMM: 128x128 tile, occ 2, 3-stage, GBK=64 -------------
// C[M,N] = A[M,K] @ B[N,K]^T + bias[n]
#define GBM 128
#define GBN 128
#define GBK 64
#define AROW 72                    // 64 + 8 pad halves (144B stride, ldsm conflict-free)
#define ASTG (GBM * AROW)          // 9216 halves / stage / matrix
#define NSTG 3
#define GSMEM (NSTG * ASTG * 2 * 2)   // 110592 B

__global__ __launch_bounds__(256, 2)
void gemm_f16(const __half* __restrict__ A, const __half* __restrict__ Bm,
              const float* __restrict__ bias, float* __restrict__ C,
              int M, int N, int K)
{
    extern __shared__ __half gsm[];
    __half* As = gsm;
    __half* Bs = gsm + NSTG * ASTG;
    const int tid = threadIdx.x;
    const int m0 = blockIdx.y * GBM, n0 = blockIdx.x * GBN;
    const int warp = tid >> 5, lane = tid & 31;
    const int wm = warp >> 2, wn = warp & 3;     // 2 x 4 warps -> 64 x 32 per warp

    float acc[4][4][4] = {};
    const int KT = K / GBK;

    // per stage: A 1024 chunks of 16B, B 1024 chunks -> 4+4 per thread
    auto stage_ld = [&](int st, int kt){
        const int k0 = kt * GBK;
        #pragma unroll
        for (int i = 0; i < 4; i++){
            int c = tid + i * 256;
            int row = c >> 3, sg = c & 7;
            int ar = m0 + row; if (ar >= M) ar = M - 1;
            cp_async16(&As[st * ASTG + row * AROW + sg * 8], A + (size_t)ar * K + k0 + sg * 8);
        }
        #pragma unroll
        for (int i = 0; i < 4; i++){
            int c = tid + i * 256;
            int row = c >> 3, sg = c & 7;
            cp_async16(&Bs[st * ASTG + row * AROW + sg * 8], Bm + (size_t)(n0 + row) * K + k0 + sg * 8);
        }
    };

    stage_ld(0, 0);
    asm volatile("cp.async.commit_group;");
    if (KT > 1){ stage_ld(1, 1); asm volatile("cp.async.commit_group;"); }

    for (int kt = 0; kt < KT; ++kt){
        const int st = kt % NSTG;
        if (kt < KT - 1) asm volatile("cp.async.wait_group 1;");
        else             asm volatile("cp.async.wait_group 0;");
        __syncthreads();
        if (kt + 2 < KT){
            stage_ld((kt + 2) % NSTG, kt + 2);
            asm volatile("cp.async.commit_group;");
        }
        #pragma unroll
        for (int kk = 0; kk < 4; kk++){
            unsigned a[4][4];
            #pragma unroll
            for (int mi = 0; mi < 4; mi++){
                const __half* p = &As[st * ASTG + (wm * 64 + mi * 16 + (lane & 15)) * AROW
                                      + kk * 16 + (lane >> 4) * 8];
                ldsm4(a[mi][0], a[mi][1], a[mi][2], a[mi][3], p);
            }
            unsigned bfr[2][4];
            #pragma unroll
            for (int nj = 0; nj < 2; nj++){
                const __half* p = &Bs[st * ASTG + (wn * 32 + nj * 16 + (lane & 15)) * AROW
                                      + kk * 16 + (lane >> 4) * 8];
                ldsm4(bfr[nj][0], bfr[nj][1], bfr[nj][2], bfr[nj][3], p);
            }
            #pragma unroll
            for (int mi = 0; mi < 4; mi++)
                #pragma unroll
                for (int ni = 0; ni < 4; ni++){
                    unsigned b0 = bfr[ni >> 1][(ni & 1)];
                    unsigned b1 = bfr[ni >> 1][(ni & 1) + 2];
                    mma16816(acc[mi][ni], a[mi][0], a[mi][1], a[mi][2], a[mi][3], b0, b1);
                }
        }
    }

    const int mrow0 = m0 + wm * 64;
    #pragma unroll
    for (int mi = 0; mi < 4; mi++)
        #pragma unroll
        for (int ni = 0; ni < 4; ni++){
            int r0 = mrow0 + mi * 16 + (lane >> 2);
            int cc = n0 + wn * 32 + ni * 8 + (lane & 3) * 2;
            float b0f = bias[cc], b1f = bias[cc + 1];
            if (r0 < M){
                float2 v = {acc[mi][ni][0] + b0f, acc[mi][ni][1] + b1f};
                *(float2*)&C[(size_t)r0 * N + cc] = v;
            }
            int r1 = r0 + 8;
            if (r1 < M){
                float2 v = {acc[mi][ni][2] + b0f, acc[mi][ni][3] + b1f};
                *(float2*)&C[(size_t)r1 * N + cc] = v;
            }
        }
}

// ---------------- persistent GRU scan: 128 CTAs x 192 threads (R6 structure) -------
// CTA owns 8 hidden units; 6 warps: nt = warp>>1 (0..2), kh = warp&1 (512-wide half).
// R6 barrier verbatim (threadfence + atomicAdd + single volatile poll).
#define SC_CTAS 128
#define SC_THREADS 192
#define HSTR 1032

__global__ __launch_bounds__(SC_THREADS, 1)
void gru_scan(const float* __restrict__ brec, const float* __restrict__ h0)
{
    extern __shared__ __half sdyn[];
    __half* hU = sdyn;                          // 24 * HSTR halves
    __half* hA = hU + 24 * HSTR;                // 16 * HSTR halves
    float*  rec0 = (float*)(hA + 16 * HSTR);    // [16][24] (kh=0)
    float*  rec1 = rec0 + 16 * 24;              // [16][24] (kh=1)

    const int tid = threadIdx.x;
    const int cta = blockIdx.x;
    const int warp = tid >> 5, lane = tid & 31;
    const int nt = warp >> 1;
    const int kh = warp & 1;
    float* recw = kh ? rec1 : rec0;

    for (int c = tid; c < 24 * 128; c += SC_THREADS){
        int j = c >> 7, seg = (c & 127) * 8;
        int gate = j >> 3, u = j & 7;
        *(int4*)&hU[j * HSTR + seg] =
            *(const int4*)&g_Ut[(size_t)(gate * HH + cta * 8 + u) * HH + seg];
    }

    float h_state = 0.f, bz = 0.f, br_ = 0.f, bh = 0.f;
    float xzc = 0.f, xrc = 0.f, xhc = 0.f;
    int b = 0, u = 0, iglob = 0;
    if (tid < 128){
        b = tid >> 3; u = tid & 7; iglob = cta * 8 + u;
        h_state = h0[b * HH + iglob];
        bz  = brec[iglob];
        br_ = brec[HH + iglob];
        bh  = brec[2 * HH + iglob];
        const size_t xrow = (size_t)(b * TT + 0) * H3;
        xzc = __ldcg(&g_xproj[xrow + iglob]);
        xrc = __ldcg(&g_xproj[xrow + HH + iglob]);
        xhc = __ldcg(&g_xproj[xrow + 2 * HH + iglob]);
    }
    __syncthreads();

    const __half* pa_base = hA + (lane & 15) * HSTR + (lane >> 4) * 8;
    const __half* pb_base = hU + (nt * 8 + (lane & 7)) * HSTR + ((lane >> 3) & 1) * 8;

    for (int t = 0; t < TT; ++t){
        const int cur = t & 1, nxt = cur ^ 1;

        // stage h[16][1024] fp16 into smem (bypass non-coherent L1)
        for (int c = tid; c < 16 * 128; c += SC_THREADS){
            int row = c >> 7, seg = (c & 127) * 8;
            int4 v = __ldcv((const int4*)&g_h[cur][row * HH + seg]);
            *(int4*)&hA[row * HSTR + seg] = v;
        }
        __syncthreads();

        // rec(kh) = h[16, khalf] @ Ustrip[24, khalf]^T  (4 rotating accums)
        float a4[4][4] = {};
        #pragma unroll
        for (int ks = 0; ks < 32; ++ks){
            int gk = kh * 32 + ks;
            unsigned A0, A1, A2, A3, B0, B1;
            ldsm4(A0, A1, A2, A3, pa_base + gk * 16);
            ldsm2(B0, B1, pb_base + gk * 16);
            mma16816(a4[ks & 3], A0, A1, A2, A3, B0, B1);
        }
        #pragma unroll
        for (int i = 0; i < 4; i++) a4[0][i] += a4[1][i] + a4[2][i] + a4[3][i];

        {
            int r = lane >> 2, c = nt * 8 + (lane & 3) * 2;
            recw[r * 24 + c]           = a4[0][0];
            recw[r * 24 + c + 1]       = a4[0][1];
            recw[(r + 8) * 24 + c]     = a4[0][2];
            recw[(r + 8) * 24 + c + 1] = a4[0][3];
        }
        __syncthreads();

        if (tid < 128){
            float rz = rec0[b * 24 + u]      + rec1[b * 24 + u]      + bz;
            float rr = rec0[b * 24 + 8 + u]  + rec1[b * 24 + 8 + u]  + br_;
            float rh = rec0[b * 24 + 16 + u] + rec1[b * 24 + 16 + u] + bh;
            float z  = 1.f / (1.f + __expf(-(xzc + rz)));
            float r_ = 1.f / (1.f + __expf(-(xrc + rr)));
            float hh = tanhf(xhc + r_ * rh);
            h_state = z * h_state + (1.f - z) * hh;
            __half hv = __float2half(h_state);
            g_h[nxt][b * HH + iglob] = hv;
            g_hs[(size_t)(b * TT + t) * HH + iglob] = hv;
            if (t + 1 < TT){     // prefetch next step's x-projection before the barrier
                const size_t xrow = (size_t)(b * TT + t + 1) * H3;
                xzc = __ldcg(&g_xproj[xrow + iglob]);
                xrc = __ldcg(&g_xproj[xrow + HH + iglob]);
                xhc = __ldcg(&g_xproj[xrow + 2 * HH + iglob]);
            }
        }
        if (t < TT - 1){
            __threadfence();
            __syncthreads();
            if (tid == 0){
                atomicAdd(&g_bar, 1u);
                unsigned target = (unsigned)(SC_CTAS * (t + 1));
                volatile unsigned* p = &g_bar;
                while (*p < target) {}
            }
            __syncthreads();
        }
    }
}

// ---------------- launch ----------------
extern "C" void kernel_launch(void* const* d_in, const int* in_sizes, int n_in,
                              void* d_out, int out_size)
{
    const int*   tok = (const int*)  d_in[0];
    const float* h0  = (const float*)d_in[1];
    const float* emb = (const float*)d_in[2];
    const float* W   = (const float*)d_in[3];
    const float* U   = (const float*)d_in[4];
    const float* bb  = (const float*)d_in[5];
    const float* Wo  = (const float*)d_in[6];
    const float* bo  = (const float*)d_in[7];
    float* out = (float*)d_out;

    void *pWt, *pUt, *pWot, *px, *pxp, *phs;
    cudaGetSymbolAddress(&pWt,  g_Wt);
    cudaGetSymbolAddress(&pUt,  g_Ut);
    cudaGetSymbolAddress(&pWot, g_Wot);
    cudaGetSymbolAddress(&px,   g_x);
    cudaGetSymbolAddress(&pxp,  g_xproj);
    cudaGetSymbolAddress(&phs,  g_hs);

    cudaFuncSetAttribute(gemm_f16, cudaFuncAttributeMaxDynamicSharedMemorySize, GSMEM);
    const int scan_smem = (24 + 16) * HSTR * (int)sizeof(__half)
                        + 2 * 16 * 24 * (int)sizeof(float);   // 85632 B
    cudaFuncSetAttribute(gru_scan, cudaFuncAttributeMaxDynamicSharedMemorySize, scan_smem);

    transpose_all<<<dim3(VV / 32, 32, 3), dim3(32, 8)>>>(W, U, Wo);
    gather_init<<<MM, 128>>>(tok, emb, h0);
    // x_proj = x @ W + b[0]   (M=4000, N=3072, K=512)
    gemm_f16<<<dim3(H3 / GBN, (MM + GBM - 1) / GBM), 256, GSMEM>>>(
        (const __half*)px, (const __half*)pWt, bb, (float*)pxp, MM, H3, EE);
    // GRU scan (persistent, grid-barriered)
    gru_scan<<<SC_CTAS, SC_THREADS, scan_smem>>>(bb + H3, h0);
    // logits = hs @ Wo + bo   (M=4000, N=32000, K=1024)
    gemm_f16<<<dim3(VV / GBN, (MM + GBM - 1) / GBM), 256, GSMEM>>>(
        (const __half*)phs, (const __half*)pWot, bo, out, MM, VV, HH);
}